// round 12
// baseline (speedup 1.0000x reference)
#include <cuda_runtime.h>
#include <cuda_fp16.h>
#include <cstdint>

// SelfConnectionIntro via baseline-PTX HMMA (mma.sync m16n8k16 f16):
// out = alpha * sum_v (opr_v ⊙ x) @ W_v   — opr FOLDED INTO A.
// R12: no epilogue. A_v[m,u] = rn16(opr[m,v]*x[m,u]) built per species into a
// double-buffered smem tile (build of v+1 interleaved into the ks-loop of v);
// HMMA accumulates directly into persistent registers across all (v,ks).
// Same error statistics as R11 (one rounding on A, one on W).

__device__ __forceinline__ uint32_t smem_u32(const void* p) {
    uint32_t a;
    asm("{ .reg .u64 t; cvta.to.shared.u64 t, %1; cvt.u32.u64 %0, t; }" : "=r"(a) : "l"(p));
    return a;
}
__device__ __forceinline__ void ldmat_x4(uint32_t r[4], uint32_t a) {
    asm volatile("ldmatrix.sync.aligned.m8n8.x4.shared.b16 {%0,%1,%2,%3}, [%4];"
                 : "=r"(r[0]), "=r"(r[1]), "=r"(r[2]), "=r"(r[3]) : "r"(a));
}
__device__ __forceinline__ void mma16816(float d[4], const uint32_t a[4],
                                         uint32_t b0, uint32_t b1) {
    asm volatile("mma.sync.aligned.m16n8k16.row.col.f32.f16.f16.f32 "
                 "{%0,%1,%2,%3},{%4,%5,%6,%7},{%8,%9},{%0,%1,%2,%3};"
                 : "+f"(d[0]), "+f"(d[1]), "+f"(d[2]), "+f"(d[3])
                 : "r"(a[0]), "r"(a[1]), "r"(a[2]), "r"(a[3]), "r"(b0), "r"(b1));
}

// B images: [v(16)][ks][nb][lane(32)] of uint2 = {b_r0, b_r1} (fp16x2 each).
__device__ uint2 BIMG0[16 * 8 * 16 * 32];
__device__ uint2 BIMG1[16 * 4 *  8 * 32];
__device__ uint2 BIMG2[16 * 2 *  4 * 32];

// W layout [U][16][NTOT]. HMMA B frag (k16 x n8): lane t, reg r, half hh:
//   u = ks*16 + 2*(t&3) + hh + r*8 ; n = nb*8 + t/4 ; value = W[u][v][n].
template<int U, int NTOT>
__global__ void prepB(const float* __restrict__ W, uint2* __restrict__ dst) {
    constexpr int KS = U / 16, NBT = NTOT / 8;
    const int total = 16 * KS * NBT * 32;
    for (int i = blockIdx.x * blockDim.x + threadIdx.x; i < total;
         i += gridDim.x * blockDim.x) {
        int lane = i & 31, r1 = i >> 5;
        int nb = r1 % NBT; r1 /= NBT;
        int ks = r1 % KS;  r1 /= KS;
        int v = r1;
        int n = nb * 8 + (lane >> 2);
        uint32_t wr[2];
#pragma unroll
        for (int r = 0; r < 2; r++) {
            uint32_t word = 0;
#pragma unroll
            for (int hh = 0; hh < 2; hh++) {
                int u = ks * 16 + 2 * (lane & 3) + hh + r * 8;
                __half h = __float2half_rn(W[((size_t)u * 16 + v) * NTOT + n]);
                word |= (uint32_t)(*(uint16_t*)&h) << (hh * 16);
            }
            wr[r] = word;
        }
        dst[i] = make_uint2(wr[0], wr[1]);
    }
}

// Main kernel. M-rows = stacked (z,k): r = z*D + k, total rows Z*D.
// CTA = 128 rows x (WN*NBW*8) output channels. Warps WM x WN, warp m32 x n(NBW*8).
template<int U, int NTOT, int D, int WM, int WN, int MW, int NBW, int OCC>
__global__ __launch_bounds__(WM * WN * 32, OCC)
void fctp_fold(const float* __restrict__ x, const float* __restrict__ opr,
               const uint2* __restrict__ Bimg, float* __restrict__ out,
               int Z, int xoff, float alpha)
{
    constexpr int KS = U / 16, NBT = NTOT / 8;
    constexpr int RS = U + 8;        // A_v row stride (halves)
    constexpr int RS32 = U + 16;     // x row stride (floats), conflict-free f4 loads
    constexpr int NTH = WM * WN * 32;
    constexpr int AR = MW * NBW * 4;
    constexpr int UD = U * D;
    constexpr int TPR = NTH / 128;   // build threads per row
    constexpr int F4 = U / TPR / 4;  // float4s per thread per full build
    constexpr int F4K = F4 / KS;     // float4s per thread per ks step
    static_assert(F4K * KS == F4, "build split");

    extern __shared__ char smraw[];
    float*  xs32 = (float*)smraw;                                    // [128][RS32]
    __half* AvA  = (__half*)(smraw + 128 * RS32 * 4);                // [128][RS]
    __half* AvB  = AvA + 128 * RS;                                   // [128][RS]
    float*  ops  = (float*)((char*)(AvB + 128 * RS));                // [128][17]

    const int tid = threadIdx.x, lane = tid & 31, wid = tid >> 5;
    const int wm = wid % WM, wn = wid / WM;
    const int moff = wm * MW * 16;
    const int nb0 = wn * NBW;
    const int rbase = blockIdx.x * 128;
    const int ZD = Z * D;

    // Tail tiles: zero x so invalid rows contribute 0 (ops also zeroed below).
    if (rbase + 128 > ZD) {
        for (int e = tid; e < 128 * RS32; e += NTH) xs32[e] = 0.0f;
        __syncthreads();
    }

    // Stage x fp32: coalesced float4 over contiguous per-z chunks, transpose-scatter.
    {
        const int z_lo = rbase / D;
        const int nchunk = (rbase + 127) / D - z_lo + 1;
        const int total4 = nchunk * (UD / 4);
        for (int q = tid; q < total4; q += NTH) {
            int f = q * 4;
            int zc = f / UD;
            int p  = f - zc * UD;
            int z  = z_lo + zc;
            if (z < Z) {
                float4 val = *(const float4*)(x + (size_t)z * 480 + xoff + p);
                float vv[4] = {val.x, val.y, val.z, val.w};
#pragma unroll
                for (int i = 0; i < 4; i++) {
                    int pi = p + i;
                    int u  = pi / D;
                    int k  = pi - u * D;
                    int m  = z * D + k - rbase;
                    if (m >= 0 && m < 128) xs32[m * RS32 + u] = vv[i];
                }
            }
        }
    }
    for (int e = tid; e < 128 * 16; e += NTH) {
        int m = e >> 4, v = e & 15;
        int z = (rbase + m) / D;
        ops[m * 17 + v] = (z < Z) ? opr[(size_t)z * 16 + v] : 0.0f;
    }
    __syncthreads();

    // Build-thread mapping: row bm, interleaved float4s (conflict-free).
    const int bm = tid / TPR, bt = tid % TPR;
    const float* xrow = xs32 + bm * RS32;

    // Full build of A_0 into AvA.
    {
        float o = ops[bm * 17];
#pragma unroll
        for (int q = 0; q < F4; q++) {
            int u = 4 * (bt + q * TPR);
            float4 a = *(const float4*)(xrow + u);
            __half2 h0 = __floats2half2_rn(o * a.x, o * a.y);
            __half2 h1 = __floats2half2_rn(o * a.z, o * a.w);
            uint2 w; w.x = *(uint32_t*)&h0; w.y = *(uint32_t*)&h1;
            *(uint2*)(AvA + bm * RS + u) = w;
        }
    }

    const uint32_t aLane = (uint32_t)(moff + (lane & 15)) * (RS * 2) + ((lane >> 4) << 4);
    const uint2* pQ = Bimg + (size_t)nb0 * 32 + lane;   // advances VSTR per v
    constexpr size_t VSTR = (size_t)KS * NBT * 32;
    constexpr size_t KSTR = (size_t)NBT * 32;

    float acc[AR];
#pragma unroll
    for (int i = 0; i < AR; i++) acc[i] = 0.0f;

    uint2 Q[2][NBW];
#pragma unroll
    for (int j = 0; j < NBW; j++) Q[0][j] = pQ[j * 32];  // (v=0, ks=0)

    __half* Acur = AvA;
    __half* Anxt = AvB;

#pragma unroll 1
    for (int v = 0; v < 16; v++) {
        __syncthreads();                       // A_v writes drained; ksloop(v-1) reads done
        const bool more = (v < 15);
        float on = more ? ops[bm * 17 + v + 1] : 0.0f;
        const uint32_t aB = smem_u32(Acur) + aLane;
        __half* dst = Anxt + bm * RS;

#pragma unroll
        for (int ks = 0; ks < KS; ks++) {
            // build chunk of A_{v+1}
            if (more) {
#pragma unroll
                for (int c = 0; c < F4K; c++) {
                    int u = 4 * (bt + (ks * F4K + c) * TPR);
                    float4 a = *(const float4*)(xrow + u);
                    __half2 h0 = __floats2half2_rn(on * a.x, on * a.y);
                    __half2 h1 = __floats2half2_rn(on * a.z, on * a.w);
                    uint2 w; w.x = *(uint32_t*)&h0; w.y = *(uint32_t*)&h1;
                    *(uint2*)(dst + u) = w;
                }
            }
            // prefetch Q
            if (ks < KS - 1) {
                const uint2* p = pQ + (size_t)(ks + 1) * KSTR;
#pragma unroll
                for (int j = 0; j < NBW; j++) Q[(ks + 1) & 1][j] = p[j * 32];
            } else if (more) {
                const uint2* p = pQ + VSTR;
#pragma unroll
                for (int j = 0; j < NBW; j++) Q[0][j] = p[j * 32];
            }
            // LDSM + MMA (accumulate straight into acc)
            uint32_t A[MW][4];
#pragma unroll
            for (int mb = 0; mb < MW; mb++)
                ldmat_x4(A[mb], aB + ks * 32 + mb * 16 * RS * 2);
#pragma unroll
            for (int mb = 0; mb < MW; mb++)
#pragma unroll
                for (int j = 0; j < NBW; j++)
                    mma16816(&acc[(mb * NBW + j) * 4], A[mb],
                             Q[ks & 1][j].x, Q[ks & 1][j].y);
        }
        __half* t = Acur; Acur = Anxt; Anxt = t;
        pQ += VSTR;
    }

    // store: row R = z*D + k
#pragma unroll
    for (int mb = 0; mb < MW; mb++) {
        int R = rbase + moff + mb * 16 + (lane >> 2);
#pragma unroll
        for (int j = 0; j < NBW; j++) {
            int n = (nb0 + j) * 8 + 2 * (lane & 3);
            float* aa = &acc[(mb * NBW + j) * 4];
            if (D == 1) {
                if (R < Z)
                    *(float2*)&out[(size_t)R * 480 + xoff + n] =
                        make_float2(alpha * aa[0], alpha * aa[1]);
                if (R + 8 < Z)
                    *(float2*)&out[(size_t)(R + 8) * 480 + xoff + n] =
                        make_float2(alpha * aa[2], alpha * aa[3]);
            } else {
                if (R < ZD) {
                    int z = R / D, k = R - z * D;
                    out[(size_t)z * 480 + xoff + n * D + k]       = alpha * aa[0];
                    out[(size_t)z * 480 + xoff + (n + 1) * D + k] = alpha * aa[1];
                }
                int R2 = R + 8;
                if (R2 < ZD) {
                    int z = R2 / D, k = R2 - z * D;
                    out[(size_t)z * 480 + xoff + n * D + k]       = alpha * aa[2];
                    out[(size_t)z * 480 + xoff + (n + 1) * D + k] = alpha * aa[3];
                }
            }
        }
    }
}

extern "C" void kernel_launch(void* const* d_in, const int* in_sizes, int n_in,
                              void* d_out, int out_size)
{
    const float* x   = (const float*)d_in[0];
    const float* opr = (const float*)d_in[1];
    const float* w0  = (const float*)d_in[2];
    const float* w1  = (const float*)d_in[3];
    const float* w2  = (const float*)d_in[4];
    float* out = (float*)d_out;

    const int Z = in_sizes[1] / 16;

    const float a0 = 0.022097086912079608f;  // 1/sqrt(128*16)
    const float a1 = 0.03125f;               // 1/sqrt(64*16)
    const float a2 = 0.044194173824159216f;  // 1/sqrt(32*16)

    void *p0, *p1, *p2;
    cudaGetSymbolAddress(&p0, BIMG0);
    cudaGetSymbolAddress(&p1, BIMG1);
    cudaGetSymbolAddress(&p2, BIMG2);

    prepB<128, 128><<<128, 256>>>(w0, (uint2*)p0);
    prepB< 64,  64><<< 32, 256>>>(w1, (uint2*)p1);
    prepB< 32,  32><<<  8, 256>>>(w2, (uint2*)p2);

    // path0: U=128, N=128, D=1; 512 thr (warps 4x4), warp m32xn32, 1 CTA/SM
    {
        constexpr int SM = 128 * 144 * 4 + 2 * 128 * 136 * 2 + 128 * 17 * 4;  // 152064
        cudaFuncSetAttribute(fctp_fold<128, 128, 1, 4, 4, 2, 4, 1>,
                             cudaFuncAttributeMaxDynamicSharedMemorySize, SM);
        fctp_fold<128, 128, 1, 4, 4, 2, 4, 1><<<(Z + 127) / 128, 512, SM>>>(
            x, opr, (const uint2*)p0, out, Z, 0, a0);
    }
    // path1: U=64, N=64, D=3; 256 thr (warps 4x2), warp m32xn32, 2 CTA/SM
    {
        constexpr int SM = 128 * 80 * 4 + 2 * 128 * 72 * 2 + 128 * 17 * 4;    // 86528
        cudaFuncSetAttribute(fctp_fold<64, 64, 3, 4, 2, 2, 4, 2>,
                             cudaFuncAttributeMaxDynamicSharedMemorySize, SM);
        fctp_fold<64, 64, 3, 4, 2, 2, 4, 2><<<(3 * Z + 127) / 128, 256, SM>>>(
            x, opr, (const uint2*)p1, out, Z, 128, a1);
    }
    // path2: U=32, N=32, D=5; 256 thr (warps 4x2), warp m32xn16, 2 CTA/SM
    {
        constexpr int SM = 128 * 48 * 4 + 2 * 128 * 40 * 2 + 128 * 17 * 4;    // 53760
        cudaFuncSetAttribute(fctp_fold<32, 32, 5, 4, 2, 2, 2, 2>,
                             cudaFuncAttributeMaxDynamicSharedMemorySize, SM);
        fctp_fold<32, 32, 5, 4, 2, 2, 2, 2><<<(5 * Z + 127) / 128, 256, SM>>>(
            x, opr, (const uint2*)p2, out, Z, 320, a2);
    }
}

// round 13
// speedup vs baseline: 1.0914x; 1.0914x over previous
#include <cuda_runtime.h>
#include <cuda_fp16.h>
#include <cstdint>

// SelfConnectionIntro via baseline-PTX HMMA (mma.sync m16n8k16 f16):
// out_l[z,w,k] = alpha * sum_v opr[z,v] * (x_l[:,:,k] @ W_l[:,v,:])[z,w]
// R13 = R11 (best) + B staged in SMEM per ks: the CTA's B slice for all 16
// species is cooperatively copied once per ks (coalesced uint4), and the
// v-loop reads Q via LDS (29 cyc) instead of LDG (~250 cyc). A frags are
// ldmatrix'd once per ks and reused across all 16 species. fp32 opr epilogue.

__device__ __forceinline__ uint32_t smem_u32(const void* p) {
    uint32_t a;
    asm("{ .reg .u64 t; cvta.to.shared.u64 t, %1; cvt.u32.u64 %0, t; }" : "=r"(a) : "l"(p));
    return a;
}
__device__ __forceinline__ void ldmat_x4(uint32_t r[4], uint32_t a) {
    asm volatile("ldmatrix.sync.aligned.m8n8.x4.shared.b16 {%0,%1,%2,%3}, [%4];"
                 : "=r"(r[0]), "=r"(r[1]), "=r"(r[2]), "=r"(r[3]) : "r"(a));
}
__device__ __forceinline__ void mma16816(float d[4], const uint32_t a[4],
                                         uint32_t b0, uint32_t b1) {
    asm volatile("mma.sync.aligned.m16n8k16.row.col.f32.f16.f16.f32 "
                 "{%0,%1,%2,%3},{%4,%5,%6,%7},{%8,%9},{%0,%1,%2,%3};"
                 : "+f"(d[0]), "+f"(d[1]), "+f"(d[2]), "+f"(d[3])
                 : "r"(a[0]), "r"(a[1]), "r"(a[2]), "r"(a[3]), "r"(b0), "r"(b1));
}
__device__ __forceinline__ void mma16816_z(float d[4], const uint32_t a[4],
                                           uint32_t b0, uint32_t b1) {
    asm volatile("mma.sync.aligned.m16n8k16.row.col.f32.f16.f16.f32 "
                 "{%0,%1,%2,%3},{%4,%5,%6,%7},{%8,%9},{%10,%11,%12,%13};"
                 : "=f"(d[0]), "=f"(d[1]), "=f"(d[2]), "=f"(d[3])
                 : "r"(a[0]), "r"(a[1]), "r"(a[2]), "r"(a[3]), "r"(b0), "r"(b1),
                   "f"(0.0f), "f"(0.0f), "f"(0.0f), "f"(0.0f));
}

// B images: [v(16)][ks][nb][lane(32)] of uint2 = {b_r0, b_r1} (fp16x2 each).
__device__ uint2 BIMG0[16 * 8 * 16 * 32];
__device__ uint2 BIMG1[16 * 4 *  8 * 32];
__device__ uint2 BIMG2[16 * 2 *  4 * 32];

// W layout [U][16][NTOT]. HMMA B frag (k16 x n8): lane t, reg r, half hh:
//   u = ks*16 + 2*(t&3) + hh + r*8 ; n = nb*8 + t/4 ; value = W[u][v][n].
template<int U, int NTOT>
__global__ void prepB(const float* __restrict__ W, uint2* __restrict__ dst) {
    constexpr int KS = U / 16, NBT = NTOT / 8;
    const int total = 16 * KS * NBT * 32;
    for (int i = blockIdx.x * blockDim.x + threadIdx.x; i < total;
         i += gridDim.x * blockDim.x) {
        int lane = i & 31, r1 = i >> 5;
        int nb = r1 % NBT; r1 /= NBT;
        int ks = r1 % KS;  r1 /= KS;
        int v = r1;
        int n = nb * 8 + (lane >> 2);
        uint32_t wr[2];
#pragma unroll
        for (int r = 0; r < 2; r++) {
            uint32_t word = 0;
#pragma unroll
            for (int hh = 0; hh < 2; hh++) {
                int u = ks * 16 + 2 * (lane & 3) + hh + r * 8;
                __half h = __float2half_rn(W[((size_t)u * 16 + v) * NTOT + n]);
                word |= (uint32_t)(*(uint16_t*)&h) << (hh * 16);
            }
            wr[r] = word;
        }
        dst[i] = make_uint2(wr[0], wr[1]);
    }
}

// One species: d = A*B; acc += opr[row,v] * d.
template<int MW, int NBW>
__device__ __forceinline__ void mma_group(
    float (&acc)[MW * NBW * 4],
    const uint32_t (&A)[MW][4],
    const uint2 (&Q)[NBW],
    const float* __restrict__ ops, int moff, int lane, int v)
{
    float d[MW * NBW * 4];
#pragma unroll
    for (int mb = 0; mb < MW; mb++)
#pragma unroll
        for (int j = 0; j < NBW; j++)
            mma16816_z(&d[(mb * NBW + j) * 4], A[mb], Q[j].x, Q[j].y);
#pragma unroll
    for (int mb = 0; mb < MW; mb++) {
        float o0 = ops[(moff + mb * 16 + (lane >> 2)) * 17 + v];
        float o1 = ops[(moff + mb * 16 + (lane >> 2) + 8) * 17 + v];
#pragma unroll
        for (int j = 0; j < NBW; j++) {
            float* dd = &d[(mb * NBW + j) * 4];
            float* aa = &acc[(mb * NBW + j) * 4];
            aa[0] = fmaf(o0, dd[0], aa[0]);
            aa[1] = fmaf(o0, dd[1], aa[1]);
            aa[2] = fmaf(o1, dd[2], aa[2]);
            aa[3] = fmaf(o1, dd[3], aa[3]);
        }
    }
}

// Main kernel. M-rows = stacked (z,k): r = z*D + k, total rows Z*D.
// CTA = 128 rows x NT channels (blockIdx.z selects NT slice of NTOT).
template<int U, int NTOT, int NT, int D, int WM, int WN, int MW, int NBW>
__global__ __launch_bounds__(WM * WN * 32, 2)
void fctp_hmma(const float* __restrict__ x, const float* __restrict__ opr,
               const uint2* __restrict__ Bimg, float* __restrict__ out,
               int Z, int xoff, float alpha)
{
    constexpr int KS = U / 16, NBT = NTOT / 8, RS = U + 8;
    constexpr int NBC = NT / 8;               // nb-blocks per CTA
    constexpr int NTH = WM * WN * 32;
    constexpr int XB = 128 * RS * 2;
    constexpr int AR = MW * NBW * 4;
    constexpr int UD = U * D;
    constexpr int BS_U2 = 16 * NBC * 32;      // Bs elements (uint2) per ks

    extern __shared__ char smraw[];
    __half* xs  = (__half*)smraw;                          // [128][RS] fp16
    float*  ops = (float*)(smraw + XB);                    // [128][17]
    uint2*  Bs  = (uint2*)(smraw + XB + 128 * 17 * 4);     // [16][NBC][32]

    const int tid = threadIdx.x, lane = tid & 31, wid = tid >> 5;
    const int wm = wid % WM, wn = wid / WM;
    const int moff = wm * MW * 16;
    const int nb0l = wn * NBW;                 // local nb within CTA slice
    const int nb0g = blockIdx.z * NBC + nb0l;  // global nb (for store)
    const int rbase = blockIdx.x * 128;
    const int ZD = Z * D;

    // Tail tiles: zero-fill A so invalid rows contribute 0.
    if (rbase + 128 > ZD) {
        for (int e = tid; e < 128 * RS / 2; e += NTH)
            ((uint32_t*)xs)[e] = 0u;
        __syncthreads();
    }

    // Stage x fp16: coalesced float4 over contiguous per-z chunks, transpose-scatter.
    {
        const int z_lo = rbase / D;
        const int nchunk = (rbase + 127) / D - z_lo + 1;
        const int total4 = nchunk * (UD / 4);
        for (int q = tid; q < total4; q += NTH) {
            int f = q * 4;
            int zc = f / UD;
            int p  = f - zc * UD;
            int z  = z_lo + zc;
            if (z < Z) {
                float4 val = *(const float4*)(x + (size_t)z * 480 + xoff + p);
                float vv[4] = {val.x, val.y, val.z, val.w};
#pragma unroll
                for (int i = 0; i < 4; i++) {
                    int pi = p + i;
                    int u  = pi / D;
                    int k  = pi - u * D;
                    int m  = z * D + k - rbase;
                    if (m >= 0 && m < 128)
                        xs[m * RS + u] = __float2half_rn(vv[i]);
                }
            }
        }
    }
    for (int e = tid; e < 128 * 16; e += NTH) {
        int m = e >> 4, v = e & 15;
        int z = (rbase + m) / D;
        ops[m * 17 + v] = (z < Z) ? opr[(size_t)z * 16 + v] : 0.0f;
    }

    const uint32_t xB = smem_u32(xs);
    const uint32_t aLane = (uint32_t)(moff + (lane & 15)) * (RS * 2) + ((lane >> 4) << 4);
    const int zoff = blockIdx.z * NBC * 32;    // uint2 offset of CTA's nb slice

    float acc[AR];
#pragma unroll
    for (int i = 0; i < AR; i++) acc[i] = 0.0f;

#pragma unroll 1
    for (int ks = 0; ks < KS; ks++) {
        __syncthreads();   // previous ks reads of Bs done (also orders staging at ks=0)
        // Cooperative B stage: 16 species x NBC nb-blocks x 32 lanes (uint4 copies)
        {
            uint4* Bs4 = (uint4*)Bs;
            constexpr int C4 = BS_U2 / 2;           // uint4 count
            constexpr int PERV = NBC * 16;          // uint4 per species chunk
#pragma unroll 1
            for (int i = tid; i < C4; i += NTH) {
                int v = i / PERV, r4 = i - v * PERV;
                const uint4* src = (const uint4*)(Bimg + (size_t)(v * KS + ks) * (NBT * 32) + zoff);
                Bs4[i] = src[r4];
            }
        }
        __syncthreads();

        // A frags for this ks, reused across all 16 species.
        uint32_t A[MW][4];
        uint32_t ba = xB + aLane + ks * 32;
#pragma unroll
        for (int mb = 0; mb < MW; mb++)
            ldmat_x4(A[mb], ba + mb * 16 * RS * 2);

#pragma unroll 2
        for (int v = 0; v < 16; v++) {
            const uint2* q = Bs + (v * NBC + nb0l) * 32 + lane;
            uint2 Q[NBW];
#pragma unroll
            for (int j = 0; j < NBW; j++) Q[j] = q[j * 32];
            mma_group<MW, NBW>(acc, A, Q, ops, moff, lane, v);
        }
    }

    // store: row R = z*D + k
#pragma unroll
    for (int mb = 0; mb < MW; mb++) {
        int R = rbase + moff + mb * 16 + (lane >> 2);
#pragma unroll
        for (int j = 0; j < NBW; j++) {
            int n = (nb0g + j) * 8 + 2 * (lane & 3);
            float* aa = &acc[(mb * NBW + j) * 4];
            if (D == 1) {
                if (R < Z)
                    *(float2*)&out[(size_t)R * 480 + xoff + n] =
                        make_float2(alpha * aa[0], alpha * aa[1]);
                if (R + 8 < Z)
                    *(float2*)&out[(size_t)(R + 8) * 480 + xoff + n] =
                        make_float2(alpha * aa[2], alpha * aa[3]);
            } else {
                if (R < ZD) {
                    int z = R / D, k = R - z * D;
                    out[(size_t)z * 480 + xoff + n * D + k]       = alpha * aa[0];
                    out[(size_t)z * 480 + xoff + (n + 1) * D + k] = alpha * aa[1];
                }
                int R2 = R + 8;
                if (R2 < ZD) {
                    int z = R2 / D, k = R2 - z * D;
                    out[(size_t)z * 480 + xoff + n * D + k]       = alpha * aa[2];
                    out[(size_t)z * 480 + xoff + (n + 1) * D + k] = alpha * aa[3];
                }
            }
        }
    }
}

extern "C" void kernel_launch(void* const* d_in, const int* in_sizes, int n_in,
                              void* d_out, int out_size)
{
    const float* x   = (const float*)d_in[0];
    const float* opr = (const float*)d_in[1];
    const float* w0  = (const float*)d_in[2];
    const float* w1  = (const float*)d_in[3];
    const float* w2  = (const float*)d_in[4];
    float* out = (float*)d_out;

    const int Z = in_sizes[1] / 16;

    const float a0 = 0.022097086912079608f;  // 1/sqrt(128*16)
    const float a1 = 0.03125f;               // 1/sqrt(64*16)
    const float a2 = 0.044194173824159216f;  // 1/sqrt(32*16)

    void *p0, *p1, *p2;
    cudaGetSymbolAddress(&p0, BIMG0);
    cudaGetSymbolAddress(&p1, BIMG1);
    cudaGetSymbolAddress(&p2, BIMG2);

    prepB<128, 128><<<128, 256>>>(w0, (uint2*)p0);
    prepB< 64,  64><<< 32, 256>>>(w1, (uint2*)p1);
    prepB< 32,  32><<<  8, 256>>>(w2, (uint2*)p2);

    // path0: U=128, N=128, D=1; NT=64 (grid.z=2); 256 thr, warps 4x2, m32xn32
    {
        constexpr int SM = 128 * 136 * 2 + 128 * 17 * 4 + 16 * 8 * 32 * 8;  // 76288
        cudaFuncSetAttribute(fctp_hmma<128, 128, 64, 1, 4, 2, 2, 4>,
                             cudaFuncAttributeMaxDynamicSharedMemorySize, SM);
        dim3 grid((Z + 127) / 128, 1, 2);
        fctp_hmma<128, 128, 64, 1, 4, 2, 2, 4><<<grid, 256, SM>>>(
            x, opr, (const uint2*)p0, out, Z, 0, a0);
    }
    // path1: U=64, N=64, D=3; NT=64; 256 thr, warps 4x2, m32xn32
    {
        constexpr int SM = 128 * 72 * 2 + 128 * 17 * 4 + 16 * 8 * 32 * 8;   // 59904
        cudaFuncSetAttribute(fctp_hmma<64, 64, 64, 3, 4, 2, 2, 4>,
                             cudaFuncAttributeMaxDynamicSharedMemorySize, SM);
        dim3 grid((3 * Z + 127) / 128, 1, 1);
        fctp_hmma<64, 64, 64, 3, 4, 2, 2, 4><<<grid, 256, SM>>>(
            x, opr, (const uint2*)p1, out, Z, 128, a1);
    }
    // path2: U=32, N=32, D=5; NT=32; 256 thr, warps 4x2, m32xn16
    {
        constexpr int SM = 128 * 40 * 2 + 128 * 17 * 4 + 16 * 4 * 32 * 8;   // 35328
        cudaFuncSetAttribute(fctp_hmma<32, 32, 32, 5, 4, 2, 2, 2>,
                             cudaFuncAttributeMaxDynamicSharedMemorySize, SM);
        dim3 grid((5 * Z + 127) / 128, 1, 1);
        fctp_hmma<32, 32, 32, 5, 4, 2, 2, 2><<<grid, 256, SM>>>(
            x, opr, (const uint2*)p2, out, Z, 320, a2);
    }
}

// round 14
// speedup vs baseline: 1.5066x; 1.3803x over previous
#include <cuda_runtime.h>
#include <cuda_fp16.h>
#include <cstdint>

// SelfConnectionIntro via baseline-PTX HMMA (mma.sync m16n8k16 f16):
// out_l[z,w,k] = alpha * sum_v opr[z,v] * (x_l[:,:,k] @ W_l[:,v,:])[z,w]
// R14: v-OUTER / ks-INNER. d_v accumulates over the whole K dim inside the
// MMA accumulator chain; the fp32 opr epilogue runs ONCE PER SPECIES
// (512 FFMA/warp instead of 4096). A frags are re-ldmatrix'd per (v,ks)
// (smem BW has 2x headroom); B via direct LDG.64 with Q0/Q1 prefetch (R11).

__device__ __forceinline__ uint32_t smem_u32(const void* p) {
    uint32_t a;
    asm("{ .reg .u64 t; cvta.to.shared.u64 t, %1; cvt.u32.u64 %0, t; }" : "=r"(a) : "l"(p));
    return a;
}
__device__ __forceinline__ void ldmat_x4(uint32_t r[4], uint32_t a) {
    asm volatile("ldmatrix.sync.aligned.m8n8.x4.shared.b16 {%0,%1,%2,%3}, [%4];"
                 : "=r"(r[0]), "=r"(r[1]), "=r"(r[2]), "=r"(r[3]) : "r"(a));
}
__device__ __forceinline__ void mma16816(float d[4], const uint32_t a[4],
                                         uint32_t b0, uint32_t b1) {
    asm volatile("mma.sync.aligned.m16n8k16.row.col.f32.f16.f16.f32 "
                 "{%0,%1,%2,%3},{%4,%5,%6,%7},{%8,%9},{%0,%1,%2,%3};"
                 : "+f"(d[0]), "+f"(d[1]), "+f"(d[2]), "+f"(d[3])
                 : "r"(a[0]), "r"(a[1]), "r"(a[2]), "r"(a[3]), "r"(b0), "r"(b1));
}
__device__ __forceinline__ void mma16816_z(float d[4], const uint32_t a[4],
                                           uint32_t b0, uint32_t b1) {
    asm volatile("mma.sync.aligned.m16n8k16.row.col.f32.f16.f16.f32 "
                 "{%0,%1,%2,%3},{%4,%5,%6,%7},{%8,%9},{%10,%11,%12,%13};"
                 : "=f"(d[0]), "=f"(d[1]), "=f"(d[2]), "=f"(d[3])
                 : "r"(a[0]), "r"(a[1]), "r"(a[2]), "r"(a[3]), "r"(b0), "r"(b1),
                   "f"(0.0f), "f"(0.0f), "f"(0.0f), "f"(0.0f));
}

// B images: [v(16)][ks][nb][lane(32)] of uint2 = {b_r0, b_r1} (fp16x2 each).
__device__ uint2 BIMG0[16 * 8 * 16 * 32];
__device__ uint2 BIMG1[16 * 4 *  8 * 32];
__device__ uint2 BIMG2[16 * 2 *  4 * 32];

// W layout [U][16][NTOT]. HMMA B frag (k16 x n8): lane t, reg r, half hh:
//   u = ks*16 + 2*(t&3) + hh + r*8 ; n = nb*8 + t/4 ; value = W[u][v][n].
template<int U, int NTOT>
__global__ void prepB(const float* __restrict__ W, uint2* __restrict__ dst) {
    constexpr int KS = U / 16, NBT = NTOT / 8;
    const int total = 16 * KS * NBT * 32;
    for (int i = blockIdx.x * blockDim.x + threadIdx.x; i < total;
         i += gridDim.x * blockDim.x) {
        int lane = i & 31, r1 = i >> 5;
        int nb = r1 % NBT; r1 /= NBT;
        int ks = r1 % KS;  r1 /= KS;
        int v = r1;
        int n = nb * 8 + (lane >> 2);
        uint32_t wr[2];
#pragma unroll
        for (int r = 0; r < 2; r++) {
            uint32_t word = 0;
#pragma unroll
            for (int hh = 0; hh < 2; hh++) {
                int u = ks * 16 + 2 * (lane & 3) + hh + r * 8;
                __half h = __float2half_rn(W[((size_t)u * 16 + v) * NTOT + n]);
                word |= (uint32_t)(*(uint16_t*)&h) << (hh * 16);
            }
            wr[r] = word;
        }
        dst[i] = make_uint2(wr[0], wr[1]);
    }
}

// Main kernel. M-rows = stacked (z,k): r = z*D + k, total rows Z*D.
// CTA = 128 rows x NT channels (blockIdx.z selects NT slice of NTOT).
template<int U, int NTOT, int NT, int D, int WM, int WN, int MW, int NBW>
__global__ __launch_bounds__(WM * WN * 32, 2)
void fctp_hmma(const float* __restrict__ x, const float* __restrict__ opr,
               const uint2* __restrict__ Bimg, float* __restrict__ out,
               int Z, int xoff, float alpha)
{
    constexpr int KS = U / 16, NBT = NTOT / 8, RS = U + 8;
    constexpr int NTH = WM * WN * 32;
    constexpr int XB = 128 * RS * 2;
    constexpr int AR = MW * NBW * 4;
    constexpr int UD = U * D;

    extern __shared__ char smraw[];
    __half* xs  = (__half*)smraw;                          // [128][RS] fp16
    float*  ops = (float*)(smraw + XB);                    // [128][17]

    const int tid = threadIdx.x, lane = tid & 31, wid = tid >> 5;
    const int wm = wid % WM, wn = wid / WM;
    const int moff = wm * MW * 16;
    const int nb0 = blockIdx.z * (NT / 8) + wn * NBW;
    const int rbase = blockIdx.x * 128;
    const int ZD = Z * D;

    // Tail tiles: zero-fill A so invalid rows contribute 0.
    if (rbase + 128 > ZD) {
        for (int e = tid; e < 128 * RS / 2; e += NTH)
            ((uint32_t*)xs)[e] = 0u;
        __syncthreads();
    }

    // Stage x fp16: coalesced float4 over contiguous per-z chunks, transpose-scatter.
    {
        const int z_lo = rbase / D;
        const int nchunk = (rbase + 127) / D - z_lo + 1;
        const int total4 = nchunk * (UD / 4);
        for (int q = tid; q < total4; q += NTH) {
            int f = q * 4;
            int zc = f / UD;
            int p  = f - zc * UD;
            int z  = z_lo + zc;
            if (z < Z) {
                float4 val = *(const float4*)(x + (size_t)z * 480 + xoff + p);
                float vv[4] = {val.x, val.y, val.z, val.w};
#pragma unroll
                for (int i = 0; i < 4; i++) {
                    int pi = p + i;
                    int u  = pi / D;
                    int k  = pi - u * D;
                    int m  = z * D + k - rbase;
                    if (m >= 0 && m < 128)
                        xs[m * RS + u] = __float2half_rn(vv[i]);
                }
            }
        }
    }
    for (int e = tid; e < 128 * 16; e += NTH) {
        int m = e >> 4, v = e & 15;
        int z = (rbase + m) / D;
        ops[m * 17 + v] = (z < Z) ? opr[(size_t)z * 16 + v] : 0.0f;
    }
    __syncthreads();

    const uint32_t xB = smem_u32(xs);
    const uint32_t aLane = (uint32_t)(moff + (lane & 15)) * (RS * 2) + ((lane >> 4) << 4);
    const uint2* pB = Bimg + (size_t)nb0 * 32 + lane;   // +((v*KS+ks)*NBT + j)*32
    constexpr size_t KSTR = (size_t)NBT * 32;

    float acc[AR];
#pragma unroll
    for (int i = 0; i < AR; i++) acc[i] = 0.0f;

    uint2 Q[2][NBW];
#pragma unroll
    for (int j = 0; j < NBW; j++) Q[0][j] = pB[j * 32];  // (v=0, ks=0)

#pragma unroll 1
    for (int v = 0; v < 16; v++) {
        float d[AR];

#pragma unroll
        for (int ks = 0; ks < KS; ks++) {
            // prefetch next B frag group: (v, ks+1) or (v+1, 0); parity (ks+1)&1.
            // KS is even for all paths, so each v starts reading Q[0]. 
            {
                int nidx = (ks + 1 < KS) ? (v * KS + ks + 1)
                                         : ((v + 1) * KS);
                if (ks + 1 < KS || v < 15) {
                    const uint2* p = pB + (size_t)nidx * KSTR;
#pragma unroll
                    for (int j = 0; j < NBW; j++) Q[(ks + 1) & 1][j] = p[j * 32];
                }
            }
            // A frags for this ks (depend on ks only)
            uint32_t A[MW][4];
            uint32_t ba = xB + aLane + ks * 32;
#pragma unroll
            for (int mb = 0; mb < MW; mb++)
                ldmat_x4(A[mb], ba + mb * 16 * RS * 2);
            // MMA: accumulate into d across ks (fresh at ks==0)
#pragma unroll
            for (int mb = 0; mb < MW; mb++)
#pragma unroll
                for (int j = 0; j < NBW; j++) {
                    float* dd = &d[(mb * NBW + j) * 4];
                    if (ks == 0)
                        mma16816_z(dd, A[mb], Q[0][j].x, Q[0][j].y);
                    else
                        mma16816(dd, A[mb], Q[ks & 1][j].x, Q[ks & 1][j].y);
                }
        }

        // epilogue ONCE per v: acc += opr[row,v] * d
#pragma unroll
        for (int mb = 0; mb < MW; mb++) {
            float o0 = ops[(moff + mb * 16 + (lane >> 2)) * 17 + v];
            float o1 = ops[(moff + mb * 16 + (lane >> 2) + 8) * 17 + v];
#pragma unroll
            for (int j = 0; j < NBW; j++) {
                float* dd = &d[(mb * NBW + j) * 4];
                float* aa = &acc[(mb * NBW + j) * 4];
                aa[0] = fmaf(o0, dd[0], aa[0]);
                aa[1] = fmaf(o0, dd[1], aa[1]);
                aa[2] = fmaf(o1, dd[2], aa[2]);
                aa[3] = fmaf(o1, dd[3], aa[3]);
            }
        }
    }

    // store: row R = z*D + k
#pragma unroll
    for (int mb = 0; mb < MW; mb++) {
        int R = rbase + moff + mb * 16 + (lane >> 2);
#pragma unroll
        for (int j = 0; j < NBW; j++) {
            int n = (nb0 + j) * 8 + 2 * (lane & 3);
            float* aa = &acc[(mb * NBW + j) * 4];
            if (D == 1) {
                if (R < Z)
                    *(float2*)&out[(size_t)R * 480 + xoff + n] =
                        make_float2(alpha * aa[0], alpha * aa[1]);
                if (R + 8 < Z)
                    *(float2*)&out[(size_t)(R + 8) * 480 + xoff + n] =
                        make_float2(alpha * aa[2], alpha * aa[3]);
            } else {
                if (R < ZD) {
                    int z = R / D, k = R - z * D;
                    out[(size_t)z * 480 + xoff + n * D + k]       = alpha * aa[0];
                    out[(size_t)z * 480 + xoff + (n + 1) * D + k] = alpha * aa[1];
                }
                int R2 = R + 8;
                if (R2 < ZD) {
                    int z = R2 / D, k = R2 - z * D;
                    out[(size_t)z * 480 + xoff + n * D + k]       = alpha * aa[2];
                    out[(size_t)z * 480 + xoff + (n + 1) * D + k] = alpha * aa[3];
                }
            }
        }
    }
}

extern "C" void kernel_launch(void* const* d_in, const int* in_sizes, int n_in,
                              void* d_out, int out_size)
{
    const float* x   = (const float*)d_in[0];
    const float* opr = (const float*)d_in[1];
    const float* w0  = (const float*)d_in[2];
    const float* w1  = (const float*)d_in[3];
    const float* w2  = (const float*)d_in[4];
    float* out = (float*)d_out;

    const int Z = in_sizes[1] / 16;

    const float a0 = 0.022097086912079608f;  // 1/sqrt(128*16)
    const float a1 = 0.03125f;               // 1/sqrt(64*16)
    const float a2 = 0.044194173824159216f;  // 1/sqrt(32*16)

    void *p0, *p1, *p2;
    cudaGetSymbolAddress(&p0, BIMG0);
    cudaGetSymbolAddress(&p1, BIMG1);
    cudaGetSymbolAddress(&p2, BIMG2);

    prepB<128, 128><<<128, 256>>>(w0, (uint2*)p0);
    prepB< 64,  64><<< 32, 256>>>(w1, (uint2*)p1);
    prepB< 32,  32><<<  8, 256>>>(w2, (uint2*)p2);

    // path0: U=128, N=128, D=1; NT=64 (grid.z=2); 256 thr, warps 4x2, m32xn32
    {
        constexpr int SM = 128 * 136 * 2 + 128 * 17 * 4;  // 43520
        cudaFuncSetAttribute(fctp_hmma<128, 128, 64, 1, 4, 2, 2, 4>,
                             cudaFuncAttributeMaxDynamicSharedMemorySize, SM);
        dim3 grid((Z + 127) / 128, 1, 2);
        fctp_hmma<128, 128, 64, 1, 4, 2, 2, 4><<<grid, 256, SM>>>(
            x, opr, (const uint2*)p0, out, Z, 0, a0);
    }
    // path1: U=64, N=64, D=3; NT=64; 256 thr, warps 4x2, m32xn32
    {
        constexpr int SM = 128 * 72 * 2 + 128 * 17 * 4;   // 27136
        cudaFuncSetAttribute(fctp_hmma<64, 64, 64, 3, 4, 2, 2, 4>,
                             cudaFuncAttributeMaxDynamicSharedMemorySize, SM);
        dim3 grid((3 * Z + 127) / 128, 1, 1);
        fctp_hmma<64, 64, 64, 3, 4, 2, 2, 4><<<grid, 256, SM>>>(
            x, opr, (const uint2*)p1, out, Z, 128, a1);
    }
    // path2: U=32, N=32, D=5; NT=32; 256 thr, warps 4x2, m32xn16
    {
        constexpr int SM = 128 * 40 * 2 + 128 * 17 * 4;   // 18944
        cudaFuncSetAttribute(fctp_hmma<32, 32, 32, 5, 4, 2, 2, 2>,
                             cudaFuncAttributeMaxDynamicSharedMemorySize, SM);
        dim3 grid((5 * Z + 127) / 128, 1, 1);
        fctp_hmma<32, 32, 32, 5, 4, 2, 2, 2><<<grid, 256, SM>>>(
            x, opr, (const uint2*)p2, out, Z, 320, a2);
    }
}